// round 7
// baseline (speedup 1.0000x reference)
#include <cuda_runtime.h>
#include <cuda_fp16.h>

#define SEQ 2048
#define H 1024
#define L 4
#define NSTEPS (SEQ + L - 1)
#define NBLOCKS 148
#define NTHREADS 1024
#define NTASKW 28           // warps 0..27 own tasks (7 l=0 rows + 21 l>0 rows)

// SMEM: 7*4KB + 21*8KB int8 weights = 200704 B
#define SMEM_BYTES 200704

#define QSCALE 127.0f
#define INVQ2  (1.0f / (127.0f * 127.0f))

// ------------------------- device scratch (no allocs) -------------------------
// int8 weights; per (l,i) row: byte b -> g=b>>10, c=(b>>9)&1, lane=(b>>4)&31, j=b&15
//   k = c*512 + lane*16 + j
__device__ signed char g_Wq[(size_t)L * H * 4 * H];        // 16 MB
__device__ signed char g_UHq[(size_t)(L - 1) * H * 4 * H]; // 12 MB
__device__ float g_Zin[(size_t)SEQ * 4 * H];               // [t][gate*H + i]
__device__ __align__(16) signed char g_h8[2][L * H];       // int8 h, dbl-buffered
__device__ unsigned g_count;                               // monotonic arrivals
__device__ unsigned g_done;                                // monotonic steps done

// ------------------------- weight pack: fp32 -> int8 (scale 127) --------------
__global__ void prep_weights(const float* __restrict__ Wf, const float* __restrict__ Wg,
                             const float* __restrict__ Wq, const float* __restrict__ Wc,
                             const float* __restrict__ UHf, const float* __restrict__ UHg,
                             const float* __restrict__ UHq, const float* __restrict__ UHc)
{
    const size_t WTOT = (size_t)L * H * 4 * H;
    const size_t UTOT = (size_t)(L - 1) * H * 4 * H;
    size_t idx = (size_t)blockIdx.x * blockDim.x + threadIdx.x;
    if (idx >= WTOT + UTOT) return;

    size_t j = (idx < WTOT) ? idx : idx - WTOT;
    size_t row = j >> 12;                 // l*H+i (W) or (l-1)*H+i (UH)
    int b = (int)(j & 4095);
    int g = b >> 10;
    int c = (b >> 9) & 1;
    int lane = (b >> 4) & 31;
    int jj = b & 15;
    int k = c * 512 + lane * 16 + jj;

    const float* src;
    if (idx < WTOT)
        src = (g == 0) ? Wf : (g == 1) ? Wg : (g == 2) ? Wq : Wc;
    else
        src = (g == 0) ? UHf : (g == 1) ? UHg : (g == 2) ? UHq : UHc;

    float v = src[row * H + k] * QSCALE;
    int q = __float2int_rn(v);
    q = max(-127, min(127, q));
    if (idx < WTOT) g_Wq[idx] = (signed char)q;
    else            g_UHq[j]  = (signed char)q;
}

__global__ void init_state()
{
    int tid = threadIdx.x;
    for (int i = tid; i < L * H; i += blockDim.x) {
        g_h8[0][i] = 0;
        g_h8[1][i] = 0;
    }
    if (tid == 0) { g_count = 0u; g_done = 0u; }
}

// ------------------------- Zin GEMM: C[t][g*H+i] = sum_k x[t][k] * U_g[i][k] ---
#define BM 128
#define BN 128
#define BK 16
__global__ __launch_bounds__(256) void gemm_zin(
    const float* __restrict__ A,                  // x [SEQ][H]
    const float* __restrict__ U0, const float* __restrict__ U1,
    const float* __restrict__ U2, const float* __restrict__ U3)
{
    __shared__ __align__(16) float As[BK][BM];
    __shared__ __align__(16) float Bs[BK][BN];
    const int tid = threadIdx.x;
    const int bm = blockIdx.y * BM;
    const int bn = blockIdx.x * BN;
    const int gate = bn >> 10;
    const float* Bp = ((gate == 0) ? U0 : (gate == 1) ? U1 : (gate == 2) ? U2 : U3)
                      + (size_t)(bn & (H - 1)) * H;
    const int lr = tid & 63;
    const int gq = tid >> 6;
    const int tx = tid & 15, ty = tid >> 4;

    float acc[8][8];
#pragma unroll
    for (int i = 0; i < 8; ++i)
#pragma unroll
        for (int j = 0; j < 8; ++j) acc[i][j] = 0.f;

    for (int k0 = 0; k0 < H; k0 += BK) {
        float4 a0 = *(const float4*)(A + (size_t)(bm + lr) * H + k0 + gq * 4);
        float4 a1 = *(const float4*)(A + (size_t)(bm + lr + 64) * H + k0 + gq * 4);
        float4 b0 = *(const float4*)(Bp + (size_t)lr * H + k0 + gq * 4);
        float4 b1 = *(const float4*)(Bp + (size_t)(lr + 64) * H + k0 + gq * 4);
        As[gq * 4 + 0][lr] = a0.x; As[gq * 4 + 1][lr] = a0.y;
        As[gq * 4 + 2][lr] = a0.z; As[gq * 4 + 3][lr] = a0.w;
        As[gq * 4 + 0][lr + 64] = a1.x; As[gq * 4 + 1][lr + 64] = a1.y;
        As[gq * 4 + 2][lr + 64] = a1.z; As[gq * 4 + 3][lr + 64] = a1.w;
        Bs[gq * 4 + 0][lr] = b0.x; Bs[gq * 4 + 1][lr] = b0.y;
        Bs[gq * 4 + 2][lr] = b0.z; Bs[gq * 4 + 3][lr] = b0.w;
        Bs[gq * 4 + 0][lr + 64] = b1.x; Bs[gq * 4 + 1][lr + 64] = b1.y;
        Bs[gq * 4 + 2][lr + 64] = b1.z; Bs[gq * 4 + 3][lr + 64] = b1.w;
        __syncthreads();
#pragma unroll
        for (int kk = 0; kk < BK; ++kk) {
            float4 a0r = *(const float4*)&As[kk][ty * 8];
            float4 a1r = *(const float4*)&As[kk][ty * 8 + 4];
            float4 b0r = *(const float4*)&Bs[kk][tx * 8];
            float4 b1r = *(const float4*)&Bs[kk][tx * 8 + 4];
            float ar[8] = {a0r.x, a0r.y, a0r.z, a0r.w, a1r.x, a1r.y, a1r.z, a1r.w};
            float br[8] = {b0r.x, b0r.y, b0r.z, b0r.w, b1r.x, b1r.y, b1r.z, b1r.w};
#pragma unroll
            for (int i = 0; i < 8; ++i)
#pragma unroll
                for (int j = 0; j < 8; ++j)
                    acc[i][j] = fmaf(ar[i], br[j], acc[i][j]);
        }
        __syncthreads();
    }
#pragma unroll
    for (int i = 0; i < 8; ++i) {
        int m = bm + ty * 8 + i;
        float* crow = g_Zin + (size_t)m * (4 * H) + bn + tx * 8;
#pragma unroll
        for (int j = 0; j < 8; j += 4) {
            *(float4*)(crow + j) = make_float4(acc[i][j], acc[i][j + 1],
                                               acc[i][j + 2], acc[i][j + 3]);
        }
    }
}

// ------------------------- merged monotonic grid barrier -----------------------
__device__ __forceinline__ void arrive_wait(unsigned step)
{
    __syncthreads();
    if (threadIdx.x == 0) {
        unsigned arrived;
        asm volatile("atom.release.gpu.add.u32 %0, [%1], 1;"
                     : "=r"(arrived) : "l"(&g_count) : "memory");
        const unsigned target = (step + 1u) * NBLOCKS;
        if (arrived == target - 1u) {
            asm volatile("st.release.gpu.u32 [%0], %1;"
                         :: "l"(&g_done), "r"(step + 1u) : "memory");
        } else {
            unsigned cur;
            asm volatile("ld.acquire.gpu.u32 %0, [%1];"
                         : "=r"(cur) : "l"(&g_done) : "memory");
            while (cur < step + 1u) {
                unsigned junk = cur;
#pragma unroll
                for (int z = 0; z < 14; ++z)
                    asm volatile("add.u32 %0, %0, 1;" : "+r"(junk));
                asm volatile("ld.acquire.gpu.u32 %0, [%1];"
                             : "=r"(cur) : "l"(&g_done) : "memory");
            }
        }
    }
    __syncthreads();
}

// ------------------------- int8 matvec core ------------------------------------
// One 4-gate int8 row (SMEM) dotted against h (registers, 2 uint4 per lane).
__device__ __forceinline__ void mv_dp4a(const uint4* __restrict__ wsm,
                                        uint4 h0, uint4 h1,
                                        int lane, int acc[4])
{
#pragma unroll
    for (int g = 0; g < 4; ++g) {
        uint4 w0 = wsm[(g * 2 + 0) * 32 + lane];
        acc[g] = __dp4a((int)w0.x, (int)h0.x, acc[g]);
        acc[g] = __dp4a((int)w0.y, (int)h0.y, acc[g]);
        acc[g] = __dp4a((int)w0.z, (int)h0.z, acc[g]);
        acc[g] = __dp4a((int)w0.w, (int)h0.w, acc[g]);
        uint4 w1 = wsm[(g * 2 + 1) * 32 + lane];
        acc[g] = __dp4a((int)w1.x, (int)h1.x, acc[g]);
        acc[g] = __dp4a((int)w1.y, (int)h1.y, acc[g]);
        acc[g] = __dp4a((int)w1.z, (int)h1.z, acc[g]);
        acc[g] = __dp4a((int)w1.w, (int)h1.w, acc[g]);
    }
}

// ------------------------- persistent wavefront LSTM (int8 DP4A) ---------------
__global__ __launch_bounds__(NTHREADS, 1) void lstm_main(
    const float* __restrict__ Bf, const float* __restrict__ Bg,
    const float* __restrict__ Bq, const float* __restrict__ Bc,
    float* __restrict__ out)
{
    extern __shared__ __align__(16) unsigned char smem[];

    const int tid  = threadIdx.x;
    const int lane = tid & 31;
    const int w    = tid >> 5;

    // ---- static task assignment: warp -> (l, i) ----
    int l = -1, i = 0, woff = 0;
    bool valid = false;
    if (w < 7) {
        l = 0; i = blockIdx.x * 7 + w; woff = w * 4096;
        valid = (i < H);
    } else if (w < NTASKW) {
        int j = blockIdx.x * 21 + (w - 7);
        l = 1 + (j >> 10); i = j & (H - 1);
        woff = 28672 + (w - 7) * 8192;
        valid = (j < 3 * H);
    }
    const int bi = (valid ? l * H + i : 0);

    // ---- copy this warp's weights into SMEM (once) ----
    if (valid) {
        const uint4* srcW = reinterpret_cast<const uint4*>(g_Wq + (size_t)bi * 4096);
        uint4* dstW = reinterpret_cast<uint4*>(smem + woff);
#pragma unroll 4
        for (int m = lane; m < 256; m += 32) dstW[m] = __ldcg(&srcW[m]);
        if (l > 0) {
            const uint4* srcU = reinterpret_cast<const uint4*>(
                g_UHq + (size_t)((l - 1) * H + i) * 4096);
            uint4* dstU = reinterpret_cast<uint4*>(smem + woff + 4096);
#pragma unroll 4
            for (int m = lane; m < 256; m += 32) dstU[m] = __ldcg(&srcU[m]);
        }
    }

    // ---- per-task constants & state ----
    float bias_g = 0.f;
    if (valid) {
        float b0 = Bf[bi], b1 = Bg[bi], b2 = Bq[bi], b3 = Bc[bi];
        bias_g = (lane == 0) ? b0 : (lane == 1) ? b1 : (lane == 2) ? b2 : b3;
    }
    float s_state = 0.f;

    const uint4* wsm = reinterpret_cast<const uint4*>(smem + woff);
    const uint4* usm = reinterpret_cast<const uint4*>(smem + woff + 4096);
    __syncthreads();

    for (int step = 0; step < NSTEPS; ++step) {
        const int t = step - l;
        const bool active = valid && ((unsigned)t < (unsigned)SEQ);

        if (active) {
            // ---- Zin prefetch (recurrence-independent) ----
            float zin_g = 0.f;
            if (l == 0 && lane < 4)
                zin_g = __ldcg(g_Zin + (size_t)t * (4 * H) + lane * H + i);

            // ---- h loads straight from L2 (no SMEM hop) ----
            const uint4* hgW = reinterpret_cast<const uint4*>(
                g_h8[step & 1] + l * H);
            uint4 hW0 = __ldcg(&hgW[lane]);
            uint4 hW1 = __ldcg(&hgW[32 + lane]);
            uint4 hU0, hU1;
            if (l > 0) {
                const uint4* hgU = reinterpret_cast<const uint4*>(
                    g_h8[step & 1] + (l - 1) * H);
                hU0 = __ldcg(&hgU[lane]);
                hU1 = __ldcg(&hgU[32 + lane]);
            }

            int acc[4] = {0, 0, 0, 0};
            mv_dp4a(wsm, hW0, hW1, lane, acc);
            if (l > 0) mv_dp4a(usm, hU0, hU1, lane, acc);

#pragma unroll
            for (int off = 16; off > 0; off >>= 1) {
                acc[0] += __shfl_xor_sync(0xffffffffu, acc[0], off);
                acc[1] += __shfl_xor_sync(0xffffffffu, acc[1], off);
                acc[2] += __shfl_xor_sync(0xffffffffu, acc[2], off);
                acc[3] += __shfl_xor_sync(0xffffffffu, acc[3], off);
            }

            // ---- parallel epilogue: lane g computes sigmoid of gate g ----
            int zi = (lane == 0) ? acc[0] : (lane == 1) ? acc[1]
                   : (lane == 2) ? acc[2] : acc[3];
            float Z = (float)zi * INVQ2 + bias_g + zin_g;
            float sig = 1.f / (1.f + __expf(-Z));
            float F = __shfl_sync(0xffffffffu, sig, 0);
            float G = __shfl_sync(0xffffffffu, sig, 1);
            float Q = __shfl_sync(0xffffffffu, sig, 2);
            float C = __shfl_sync(0xffffffffu, sig, 3);

            if (lane == 0) {
                s_state = fmaf(F, s_state, G * C);
                float hn = tanhf(s_state) * Q;
                int hq = __float2int_rn(hn * QSCALE);
                hq = max(-127, min(127, hq));
                unsigned hv = (unsigned)(unsigned char)(signed char)hq;
                asm volatile("st.global.cg.u8 [%0], %1;"
                             :: "l"(&g_h8[(step + 1) & 1][bi]), "r"(hv));
                if (t == SEQ - 1) out[bi] = hn;
            }
        }
        if (step < NSTEPS - 1) arrive_wait((unsigned)step);
    }
}

// ------------------------- launch ---------------------------------------------
extern "C" void kernel_launch(void* const* d_in, const int* in_sizes, int n_in,
                              void* d_out, int out_size)
{
    const float* x   = (const float*)d_in[0];
    const float* Uf  = (const float*)d_in[1];
    const float* UHf = (const float*)d_in[2];
    const float* Wf  = (const float*)d_in[3];
    const float* Bf  = (const float*)d_in[4];
    const float* Ug  = (const float*)d_in[5];
    const float* UHg = (const float*)d_in[6];
    const float* Wg  = (const float*)d_in[7];
    const float* Bg  = (const float*)d_in[8];
    const float* Uq  = (const float*)d_in[9];
    const float* UHq = (const float*)d_in[10];
    const float* Wq  = (const float*)d_in[11];
    const float* Bq  = (const float*)d_in[12];
    const float* Uc  = (const float*)d_in[13];
    const float* UHc = (const float*)d_in[14];
    const float* Wc  = (const float*)d_in[15];
    const float* Bc  = (const float*)d_in[16];
    float* out = (float*)d_out;

    cudaFuncSetAttribute(lstm_main, cudaFuncAttributeMaxDynamicSharedMemorySize,
                         SMEM_BYTES);

    const size_t TOTAL = (size_t)L * H * 4 * H + (size_t)(L - 1) * H * 4 * H;
    int pb = (int)((TOTAL + 1023) / 1024);
    prep_weights<<<pb, 1024>>>(Wf, Wg, Wq, Wc, UHf, UHg, UHq, UHc);
    init_state<<<1, 1024>>>();

    dim3 gg(4 * H / BN, SEQ / BM);
    gemm_zin<<<gg, 256>>>(x, Uf, Ug, Uq, Uc);

    lstm_main<<<NBLOCKS, NTHREADS, SMEM_BYTES>>>(Bf, Bg, Bq, Bc, out);
}